// round 5
// baseline (speedup 1.0000x reference)
#include <cuda_runtime.h>
#include <cstdio>

#define NT   343      // tokens per window (7*7*7)
#define CDIM 96       // embedding dim
#define HD   32       // head dim
#define NH   3        // heads
#define NW   64       // windows per batch group
#define BTOT 512      // total "b" (batch * windows)

typedef unsigned long long u64;

// ---------------- packed f32x2 helpers (sm_103a FFMA2) ----------------
__device__ __forceinline__ u64 pack2(float lo, float hi) {
    u64 r; asm("mov.b64 %0, {%1, %2};" : "=l"(r) : "f"(lo), "f"(hi)); return r;
}
__device__ __forceinline__ void unpack2(u64 v, float& lo, float& hi) {
    asm("mov.b64 {%0, %1}, %2;" : "=f"(lo), "=f"(hi) : "l"(v));
}
__device__ __forceinline__ u64 ffma2(u64 a, u64 b, u64 c) {
    u64 d; asm("fma.rn.f32x2 %0, %1, %2, %3;" : "=l"(d) : "l"(a), "l"(b), "l"(c)); return d;
}
__device__ __forceinline__ u64 fmul2(u64 a, u64 b) {
    u64 d; asm("mul.rn.f32x2 %0, %1, %2;" : "=l"(d) : "l"(a), "l"(b)); return d;
}

// ---------------- scratch (static device globals: allocation-free) ----------------
__device__ float g_bm[(size_t)NW * NH * NT * NT];        // bias+mask, transposed [w,h][m][n]
__device__ float g_attn[(size_t)BTOT * NT * CDIM];       // attention output before proj
__device__ float g_q[(size_t)BTOT * NH * NT * HD];       // [b,h][n][d], pre-scaled
__device__ float g_k[(size_t)BTOT * NH * NT * HD];       // [b,h][n][d]
__device__ float g_v[(size_t)BTOT * NH * NT * HD];       // [b,h][n][d]

// swizzled K/V smem offset: row m, float4-quad dq (conflict-free writes, broadcast reads)
__device__ __forceinline__ int kvoff(int m, int dq) {
    return m * HD + ((dq ^ (m & 7)) << 2);
}

// ============================ K0: bias+mask precombine (transposed) ============================
__global__ void bm_kernel(const float* __restrict__ mask,
                          const float* __restrict__ rpb,
                          const int*   __restrict__ ridx) {
    __shared__ float mt[32][33];
    __shared__ int   rt[32][33];
    const int w  = blockIdx.y;
    const int t  = blockIdx.x;            // 0..120
    const int tm = (t % 11) * 32;         // m tile base
    const int tn = (t / 11) * 32;         // n tile base
    const int tid = threadIdx.x;

    for (int i = tid; i < 1024; i += 256) {
        int r = i / 32, c = i % 32;
        int n = tn + r, m = tm + c;
        if (n < NT && m < NT) {
            mt[r][c] = mask[((size_t)w * NT + n) * NT + m];
            rt[r][c] = ridx[n * NT + m];
        }
    }
    __syncthreads();
    for (int i = tid; i < 1024; i += 256) {
        int r = i / 32, c = i % 32;
        int n = tn + c, m = tm + r;
        if (n < NT && m < NT) {
            float mv = mt[c][r];
            int   ri = rt[c][r];
#pragma unroll
            for (int hh = 0; hh < NH; hh++) {
                g_bm[(((size_t)w * NH + hh) * NT + m) * NT + n] = mv + __ldg(rpb + ri * NH + hh);
            }
        }
    }
}

// ============================ K_A: QKV GEMM (packed FFMA2) ============================
// out[t][sel*96+oc] = sum_k x[t][k] * qkv_w[sel*96+oc][k] + qkv_b[...]
// tile: 128 tokens x 96 cols per pass, 3 passes; 256 threads, thread tile 8 rows x 6 cols.
#define XS_STRIDE 100
#define WS_STRIDE 98
#define QKV_SMEM_FLOATS (128 * XS_STRIDE + CDIM * WS_STRIDE)

__global__ __launch_bounds__(256, 2)
void qkv_kernel(const float* __restrict__ x,
                const float* __restrict__ qw,
                const float* __restrict__ qb) {
    extern __shared__ float sma[];
    float* xs = sma;                       // [128][100]  row-major x tile
    float* ws = sma + 128 * XS_STRIDE;     // [96][98]    W transposed [k][oc]

    const int tid = threadIdx.x;
    const int t0  = blockIdx.x * 128;
    const float scale = 0.17677669529663689f;

    // ---- load x tile (coalesced float4, natural layout) ----
    {
        const float4* xg = (const float4*)(x + (size_t)t0 * CDIM);
#pragma unroll
        for (int j = 0; j < 12; j++) {
            int idx = tid + j * 256;           // < 3072
            int r = idx / 24, c4 = idx % 24;
            float4 v = __ldg(xg + idx);
            *(float4*)&xs[r * XS_STRIDE + c4 * 4] = v;
        }
    }

    const int tr = tid >> 4;        // 0..15  -> rows tr*8..tr*8+7
    const int tc = tid & 15;        // 0..15  -> cols tc*6..tc*6+5
    const int cb = tc * 6;

#pragma unroll 1
    for (int sel = 0; sel < 3; sel++) {
        __syncthreads();
        // load W slice transposed into ws[k][oc]
#pragma unroll
        for (int j = 0; j < 9; j++) {
            int idx = tid + j * 256;           // < 2304
            int oc = idx / 24, k4 = idx % 24;
            float4 v = __ldg((const float4*)(qw + (size_t)(sel * CDIM + oc) * CDIM) + k4);
            ws[(k4 * 4 + 0) * WS_STRIDE + oc] = v.x;
            ws[(k4 * 4 + 1) * WS_STRIDE + oc] = v.y;
            ws[(k4 * 4 + 2) * WS_STRIDE + oc] = v.z;
            ws[(k4 * 4 + 3) * WS_STRIDE + oc] = v.w;
        }
        __syncthreads();

        u64 bias0 = pack2(__ldg(qb + sel * CDIM + cb + 0), __ldg(qb + sel * CDIM + cb + 1));
        u64 bias1 = pack2(__ldg(qb + sel * CDIM + cb + 2), __ldg(qb + sel * CDIM + cb + 3));
        u64 bias2 = pack2(__ldg(qb + sel * CDIM + cb + 4), __ldg(qb + sel * CDIM + cb + 5));
        u64 acc[8][3];
#pragma unroll
        for (int i = 0; i < 8; i++) { acc[i][0] = bias0; acc[i][1] = bias1; acc[i][2] = bias2; }

#pragma unroll 4
        for (int k = 0; k < CDIM; k++) {
            u64 w0 = *(const u64*)&ws[k * WS_STRIDE + cb + 0];
            u64 w1 = *(const u64*)&ws[k * WS_STRIDE + cb + 2];
            u64 w2 = *(const u64*)&ws[k * WS_STRIDE + cb + 4];
#pragma unroll
            for (int i = 0; i < 8; i++) {
                float xv = xs[(tr * 8 + i) * XS_STRIDE + k];
                u64 xp = pack2(xv, xv);
                acc[i][0] = ffma2(xp, w0, acc[i][0]);
                acc[i][1] = ffma2(xp, w1, acc[i][1]);
                acc[i][2] = ffma2(xp, w2, acc[i][2]);
            }
        }

        float* gout = (sel == 0) ? g_q : (sel == 1) ? g_k : g_v;
        u64 sc2 = pack2(scale, scale);
#pragma unroll
        for (int i = 0; i < 8; i++) {
            int t = t0 + tr * 8 + i;
            int b = t / NT, n = t - b * NT;
            u64 a0 = acc[i][0], a1 = acc[i][1], a2 = acc[i][2];
            if (sel == 0) { a0 = fmul2(a0, sc2); a1 = fmul2(a1, sc2); a2 = fmul2(a2, sc2); }
#pragma unroll
            for (int p = 0; p < 3; p++) {
                int oc = cb + 2 * p;
                int h = oc >> 5, d = oc & 31;
                u64 av = (p == 0) ? a0 : (p == 1) ? a1 : a2;
                *(u64*)&gout[(((size_t)b * NH + h) * NT + n) * HD + d] = av;
            }
        }
    }
}

// ============================ K_B: attention (K/V in smem, 2 CTAs/SM) ============================
#define ATTN_SMEM_FLOATS (NT * HD * 2)

__global__ __launch_bounds__(352, 2)
void attn2_kernel() {
    extern __shared__ float smb[];
    float* ks = smb;              // [m][d] swizzled
    float* vs = smb + NT * HD;    // [m][d] swizzled

    const int b   = blockIdx.x;
    const int h   = blockIdx.y;
    const int tid = threadIdx.x;
    const int n   = tid;
    const size_t base = ((size_t)b * NH + h) * NT * HD;

    // ---- stage K/V into smem (coalesced float4) ----
    {
        const float4* kg = (const float4*)(g_k + base);
        const float4* vg = (const float4*)(g_v + base);
        for (int idx = tid; idx < NT * HD / 4; idx += 352) {
            int m = idx >> 3, dq = idx & 7;
            *(float4*)&ks[kvoff(m, dq)] = __ldg(kg + idx);
            *(float4*)&vs[kvoff(m, dq)] = __ldg(vg + idx);
        }
    }

    u64 q2[HD / 2];
    if (n < NT) {
        const float4* qg = (const float4*)(g_q + base + (size_t)n * HD);
#pragma unroll
        for (int dq = 0; dq < HD / 4; dq++) {
            float4 v = __ldg(qg + dq);
            q2[2 * dq + 0] = pack2(v.x, v.y);
            q2[2 * dq + 1] = pack2(v.z, v.w);
        }
    }
    __syncthreads();

    if (n < NT) {
        const float* bmrow = g_bm + (((size_t)(b % NW) * NH + h) * NT) * NT;  // [m][n]
        u64 o2[HD / 2];
#pragma unroll
        for (int i = 0; i < HD / 2; i++) o2[i] = 0ull;
        float mrun = -1e30f, lrun = 0.f;

        // 49 exact chunks of 7 keys (343 = 49*7)
#pragma unroll 1
        for (int mb = 0; mb < NT; mb += 7) {
            float s[7];
#pragma unroll
            for (int j = 0; j < 7; j++)
                s[j] = __ldg(bmrow + (size_t)(mb + j) * NT + n);   // coalesced over n
#pragma unroll
            for (int j = 0; j < 7; j++) {
                int m = mb + j;
                u64 a0 = 0ull, a1 = 0ull;
#pragma unroll
                for (int dq = 0; dq < HD / 4; dq++) {
                    ulonglong2 k2 = *(const ulonglong2*)(ks + kvoff(m, dq));  // broadcast LDS128
                    a0 = ffma2(q2[2 * dq + 0], k2.x, a0);
                    a1 = ffma2(q2[2 * dq + 1], k2.y, a1);
                }
                float l0, h0, l1, h1;
                unpack2(a0, l0, h0); unpack2(a1, l1, h1);
                s[j] += (l0 + h0) + (l1 + h1);
            }
            float cm = fmaxf(fmaxf(fmaxf(s[0], s[1]), fmaxf(s[2], s[3])),
                             fmaxf(fmaxf(s[4], s[5]), s[6]));
            float mnew = fmaxf(mrun, cm);
            float corr = __expf(mrun - mnew);
            lrun *= corr;
            u64 corr2 = pack2(corr, corr);
#pragma unroll
            for (int i = 0; i < HD / 2; i++) o2[i] = fmul2(o2[i], corr2);
#pragma unroll
            for (int j = 0; j < 7; j++) {
                int m = mb + j;
                float p = __expf(s[j] - mnew);
                lrun += p;
                u64 p2 = pack2(p, p);
#pragma unroll
                for (int dq = 0; dq < HD / 4; dq++) {
                    ulonglong2 v2 = *(const ulonglong2*)(vs + kvoff(m, dq));  // broadcast LDS128
                    o2[2 * dq + 0] = ffma2(p2, v2.x, o2[2 * dq + 0]);
                    o2[2 * dq + 1] = ffma2(p2, v2.y, o2[2 * dq + 1]);
                }
            }
            mrun = mnew;
        }

        float inv = 1.f / lrun;
        u64 inv2 = pack2(inv, inv);
        float* op = g_attn + ((size_t)b * NT + n) * CDIM + h * HD;
#pragma unroll
        for (int dq = 0; dq < HD / 4; dq++) {
            ulonglong2 t;
            t.x = fmul2(o2[2 * dq + 0], inv2);
            t.y = fmul2(o2[2 * dq + 1], inv2);
            *(ulonglong2*)(op + 4 * dq) = t;
        }
    }
}

// ============================ K2: output projection GEMM (packed) ============================
#define K2_ROWS 64
#define PW_PAD  100
#define SMEM_K2_FLOATS (CDIM*PW_PAD + K2_ROWS*CDIM)

__global__ __launch_bounds__(256)
void proj_kernel(const float* __restrict__ pw,
                 const float* __restrict__ pb,
                 float* __restrict__ out) {
    extern __shared__ float sm2[];
    float* pws = sm2;                          // [c][d], row stride 100
    float* as  = sm2 + CDIM * PW_PAD;          // [r][c]
    const int tid = threadIdx.x;
    const size_t row0 = (size_t)blockIdx.x * K2_ROWS;

    for (int i = tid; i < CDIM * CDIM; i += 256) {
        pws[(i % CDIM) * PW_PAD + (i / CDIM)] = __ldg(pw + i);
    }
    for (int i = tid; i < K2_ROWS * CDIM; i += 256) {
        as[i] = __ldg(g_attn + row0 * CDIM + i);
    }
    __syncthreads();

#pragma unroll
    for (int k = 0; k < 6; k++) {
        int idx = tid + k * 256;               // 0..1535 quads
        int r  = idx / 24;
        int d  = (idx % 24) * 4;
        u64 a0 = pack2(__ldg(pb + d + 0), __ldg(pb + d + 1));
        u64 a1 = pack2(__ldg(pb + d + 2), __ldg(pb + d + 3));
        const float* arow = as + r * CDIM;
#pragma unroll 4
        for (int c = 0; c < CDIM; c++) {
            float xv = arow[c];
            u64 xv2 = pack2(xv, xv);
            const u64* w2 = (const u64*)(pws + c * PW_PAD + d);
            a0 = ffma2(xv2, w2[0], a0);
            a1 = ffma2(xv2, w2[1], a1);
        }
        ulonglong2 t; t.x = a0; t.y = a1;
        *(ulonglong2*)(out + (row0 + r) * CDIM + d) = t;
    }
}

// ============================ launch ============================
extern "C" void kernel_launch(void* const* d_in, const int* in_sizes, int n_in,
                              void* d_out, int out_size) {
    const float* x      = (const float*)d_in[0];
    const float* mask   = (const float*)d_in[1];
    const float* qkv_w  = (const float*)d_in[2];
    const float* qkv_b  = (const float*)d_in[3];
    const float* proj_w = (const float*)d_in[4];
    const float* proj_b = (const float*)d_in[5];
    const float* rpb    = (const float*)d_in[6];
    const int*   ridx   = (const int*)d_in[7];
    float* out = (float*)d_out;

    cudaFuncSetAttribute(qkv_kernel, cudaFuncAttributeMaxDynamicSharedMemorySize,
                         QKV_SMEM_FLOATS * (int)sizeof(float));
    cudaFuncSetAttribute(attn2_kernel, cudaFuncAttributeMaxDynamicSharedMemorySize,
                         ATTN_SMEM_FLOATS * (int)sizeof(float));
    cudaFuncSetAttribute(proj_kernel, cudaFuncAttributeMaxDynamicSharedMemorySize,
                         SMEM_K2_FLOATS * (int)sizeof(float));

    bm_kernel<<<dim3(121, NW), 256>>>(mask, rpb, ridx);
    qkv_kernel<<<(BTOT * NT) / 128, 256, QKV_SMEM_FLOATS * sizeof(float)>>>(x, qkv_w, qkv_b);
    attn2_kernel<<<dim3(BTOT, NH), 352, ATTN_SMEM_FLOATS * sizeof(float)>>>();
    proj_kernel<<<(BTOT * NT) / K2_ROWS, 256, SMEM_K2_FLOATS * sizeof(float)>>>(proj_w, proj_b, out);
}

// round 6
// speedup vs baseline: 1.8025x; 1.8025x over previous
#include <cuda_runtime.h>
#include <cstdio>

#define NT   343      // tokens per window (7*7*7)
#define CDIM 96       // embedding dim
#define HD   32       // head dim
#define NH   3        // heads
#define NW   64       // windows per batch group
#define BTOT 512      // total "b" (batch * windows)

typedef unsigned long long u64;

// ---------------- packed f32x2 helpers (sm_103a FFMA2) ----------------
__device__ __forceinline__ u64 pack2(float lo, float hi) {
    u64 r; asm("mov.b64 %0, {%1, %2};" : "=l"(r) : "f"(lo), "f"(hi)); return r;
}
__device__ __forceinline__ u64 ffma2(u64 a, u64 b, u64 c) {
    u64 d; asm("fma.rn.f32x2 %0, %1, %2, %3;" : "=l"(d) : "l"(a), "l"(b), "l"(c)); return d;
}
__device__ __forceinline__ u64 fmul2(u64 a, u64 b) {
    u64 d; asm("mul.rn.f32x2 %0, %1, %2;" : "=l"(d) : "l"(a), "l"(b)); return d;
}

// ---------------- scratch (static device globals: allocation-free) ----------------
__device__ float g_bm[(size_t)NW * NH * NT * NT];        // bias+mask, [w,h][n][m]
__device__ float g_attn[(size_t)BTOT * NT * CDIM];       // attention output before proj
__device__ float g_q[(size_t)BTOT * NH * NT * HD];       // [b,h][n][d], pre-scaled
__device__ float g_k[(size_t)BTOT * NH * NT * HD];       // [b,h][n][d]
__device__ float g_v[(size_t)BTOT * NH * NT * HD];       // [b,h][n][d]

// ============================ K0: bias+mask precombine ([n][m], natural) ============================
__global__ void bm_kernel(const float* __restrict__ mask,
                          const float* __restrict__ rpb,
                          const int*   __restrict__ ridx) {
    int i = blockIdx.x * 256 + threadIdx.x;    // over NT*NT = 117649
    if (i >= NT * NT) return;
    int w = blockIdx.y;
    float mv = __ldg(mask + (size_t)w * NT * NT + i);
    int   ri = __ldg(ridx + i);
#pragma unroll
    for (int h = 0; h < NH; h++)
        g_bm[((size_t)(w * NH + h)) * NT * NT + i] = mv + __ldg(rpb + ri * NH + h);
}

// ============================ K_A: QKV GEMM (packed FFMA2) ============================
#define XS_STRIDE 100
#define WS_STRIDE 98
#define QKV_SMEM_FLOATS (128 * XS_STRIDE + CDIM * WS_STRIDE)

__global__ __launch_bounds__(256, 2)
void qkv_kernel(const float* __restrict__ x,
                const float* __restrict__ qw,
                const float* __restrict__ qb) {
    extern __shared__ float sma[];
    float* xs = sma;                       // [128][100]  row-major x tile
    float* ws = sma + 128 * XS_STRIDE;     // [96][98]    W transposed [k][oc]

    const int tid = threadIdx.x;
    const int t0  = blockIdx.x * 128;
    const float scale = 0.17677669529663689f;

    {
        const float4* xg = (const float4*)(x + (size_t)t0 * CDIM);
#pragma unroll
        for (int j = 0; j < 12; j++) {
            int idx = tid + j * 256;           // < 3072
            int r = idx / 24, c4 = idx % 24;
            float4 v = __ldg(xg + idx);
            *(float4*)&xs[r * XS_STRIDE + c4 * 4] = v;
        }
    }

    const int tr = tid >> 4;        // 0..15  -> rows tr*8..tr*8+7
    const int tc = tid & 15;        // 0..15  -> cols tc*6..tc*6+5
    const int cb = tc * 6;

#pragma unroll 1
    for (int sel = 0; sel < 3; sel++) {
        __syncthreads();
#pragma unroll
        for (int j = 0; j < 9; j++) {
            int idx = tid + j * 256;           // < 2304
            int oc = idx / 24, k4 = idx % 24;
            float4 v = __ldg((const float4*)(qw + (size_t)(sel * CDIM + oc) * CDIM) + k4);
            ws[(k4 * 4 + 0) * WS_STRIDE + oc] = v.x;
            ws[(k4 * 4 + 1) * WS_STRIDE + oc] = v.y;
            ws[(k4 * 4 + 2) * WS_STRIDE + oc] = v.z;
            ws[(k4 * 4 + 3) * WS_STRIDE + oc] = v.w;
        }
        __syncthreads();

        u64 bias0 = pack2(__ldg(qb + sel * CDIM + cb + 0), __ldg(qb + sel * CDIM + cb + 1));
        u64 bias1 = pack2(__ldg(qb + sel * CDIM + cb + 2), __ldg(qb + sel * CDIM + cb + 3));
        u64 bias2 = pack2(__ldg(qb + sel * CDIM + cb + 4), __ldg(qb + sel * CDIM + cb + 5));
        u64 acc[8][3];
#pragma unroll
        for (int i = 0; i < 8; i++) { acc[i][0] = bias0; acc[i][1] = bias1; acc[i][2] = bias2; }

#pragma unroll 4
        for (int k = 0; k < CDIM; k++) {
            u64 w0 = *(const u64*)&ws[k * WS_STRIDE + cb + 0];
            u64 w1 = *(const u64*)&ws[k * WS_STRIDE + cb + 2];
            u64 w2 = *(const u64*)&ws[k * WS_STRIDE + cb + 4];
#pragma unroll
            for (int i = 0; i < 8; i++) {
                float xv = xs[(tr * 8 + i) * XS_STRIDE + k];
                u64 xp = pack2(xv, xv);
                acc[i][0] = ffma2(xp, w0, acc[i][0]);
                acc[i][1] = ffma2(xp, w1, acc[i][1]);
                acc[i][2] = ffma2(xp, w2, acc[i][2]);
            }
        }

        float* gout = (sel == 0) ? g_q : (sel == 1) ? g_k : g_v;
        u64 sc2 = pack2(scale, scale);
#pragma unroll
        for (int i = 0; i < 8; i++) {
            int t = t0 + tr * 8 + i;
            int b = t / NT, n = t - b * NT;
            u64 a0 = acc[i][0], a1 = acc[i][1], a2 = acc[i][2];
            if (sel == 0) { a0 = fmul2(a0, sc2); a1 = fmul2(a1, sc2); a2 = fmul2(a2, sc2); }
#pragma unroll
            for (int p = 0; p < 3; p++) {
                int oc = cb + 2 * p;
                int h = oc >> 5, d = oc & 31;
                u64 av = (p == 0) ? a0 : (p == 1) ? a1 : a2;
                *(u64*)&gout[(((size_t)b * NH + h) * NT + n) * HD + d] = av;
            }
        }
    }
}

// ============================ K_B: tiled two-pass attention ============================
#define QT   64       // query rows per tile
#define SST  354      // S row stride (floats)
#define KTS  354      // kt row stride
#define QSS  36       // qs row stride (float4-aligned)

#define SM_S   0
#define SM_KT  (QT * SST)                    // 22656
#define SM_VS  (SM_KT + 32 * KTS)            // +11328 = 33984
#define SM_QS  (SM_VS + NT * 32)             // +10976 = 44960
#define SM_RED (SM_QS + NT * QSS)            // +12348 = 57308
#define SM_LI  (SM_RED + 64 * 10)            // +640   = 57948
#define ATTN3_SMEM_FLOATS (SM_LI + 64)       // 58012 floats = 232048 B

__global__ __launch_bounds__(352, 1)
void attn3_kernel() {
    extern __shared__ float sm[];
    float* S    = sm + SM_S;       // [64][354]
    float* kt   = sm + SM_KT;      // [32][354]  K transposed [d][m], cols >=343 zeroed
    float* vs   = sm + SM_VS;      // [343][32]
    float* qs   = sm + SM_QS;      // [343][36]
    float* red  = sm + SM_RED;     // [64][10]  (max in 0..4, sum in 5..9)
    float* linv = sm + SM_LI;      // [64]

    const int b   = blockIdx.x;
    const int h   = blockIdx.y;
    const int tid = threadIdx.x;
    const size_t base = ((size_t)b * NH + h) * NT * HD;

    // ---- stage Q/K/V into smem ----
    {
        const float4* kg = (const float4*)(g_k + base);
        const float4* vg = (const float4*)(g_v + base);
        const float4* qg = (const float4*)(g_q + base);
        for (int idx = tid; idx < NT * 8; idx += 352) {
            int m = idx >> 3, dq = idx & 7;
            float4 kv = __ldg(kg + idx);
            kt[(4 * dq + 0) * KTS + m] = kv.x;
            kt[(4 * dq + 1) * KTS + m] = kv.y;
            kt[(4 * dq + 2) * KTS + m] = kv.z;
            kt[(4 * dq + 3) * KTS + m] = kv.w;
            *(float4*)&vs[m * 32 + 4 * dq]  = __ldg(vg + idx);
            *(float4*)&qs[m * QSS + 4 * dq] = __ldg(qg + idx);
        }
        // zero kt pad cols 343..353 (32 rows x 11 cols = 352)
        if (tid < 352) {
            int d = tid / 11, c = tid % 11;
            kt[d * KTS + NT + c] = 0.f;
        }
    }
    const float* bmw = g_bm + ((size_t)(b % NW) * NH + h) * NT * NT;   // [n][m]
    __syncthreads();

    const int rg = tid & 15;         // S-GEMM: rows rg*4..+3
    const int cg = tid >> 4;         // 0..21 : cols cg*16..+15
    const int c0 = cg * 16;
    const int rg2 = tid >> 3;        // PV (tid<256): rows 2*rg2, 2*rg2+1
    const int dg  = tid & 7;         // PV: dims 4*dg..+3
    const int srow = tid / 5;        // softmax (tid<320)
    const int stc  = tid - srow * 5;

#pragma unroll 1
    for (int tile = 0; tile < 6; tile++) {
        const int qbase = tile * QT;

        // ---- 1. bias+mask tile -> S (lanes over cols: coalesced) ----
        {
            int c = tid;   // 0..351
            float* scol = S + c;
            if (c < NT) {
                const float* bp = bmw + c;
#pragma unroll 4
                for (int r = 0; r < QT; r++) {
                    int n = qbase + r; if (n > NT - 1) n = NT - 1;
                    scol[r * SST] = __ldg(bp + (size_t)n * NT);
                }
            } else {
#pragma unroll 4
                for (int r = 0; r < QT; r++) scol[r * SST] = -1e30f;
            }
        }
        __syncthreads();

        // ---- 2. S += Q @ K^T  (thread tile 4 rows x 16 cols, packed) ----
        {
            int r0[4];
#pragma unroll
            for (int i = 0; i < 4; i++) {
                int rr = qbase + rg * 4 + i;
                r0[i] = (rr > NT - 1) ? NT - 1 : rr;
            }
            u64 acc[4][8];
#pragma unroll
            for (int i = 0; i < 4; i++)
#pragma unroll
                for (int p = 0; p < 8; p++)
                    acc[i][p] = *(const u64*)&S[(rg * 4 + i) * SST + c0 + 2 * p];

#pragma unroll 4
            for (int d = 0; d < 32; d++) {
                u64 kb[8];
#pragma unroll
                for (int p = 0; p < 8; p++) kb[p] = *(const u64*)&kt[d * KTS + c0 + 2 * p];
#pragma unroll
                for (int i = 0; i < 4; i++) {
                    float qv = qs[r0[i] * QSS + d];
                    u64 qp = pack2(qv, qv);
#pragma unroll
                    for (int p = 0; p < 8; p++) acc[i][p] = ffma2(qp, kb[p], acc[i][p]);
                }
            }
#pragma unroll
            for (int i = 0; i < 4; i++)
#pragma unroll
                for (int p = 0; p < 8; p++)
                    *(u64*)&S[(rg * 4 + i) * SST + c0 + 2 * p] = acc[i][p];
        }
        __syncthreads();

        // ---- 3. row softmax (5 threads per row) ----
        if (tid < 320) {
            int cs = stc * 71, ce = cs + 71; if (ce > 352) ce = 352;
            const float* sr = S + srow * SST;
            float lmax = -1e30f;
            for (int c = cs; c < ce; c++) lmax = fmaxf(lmax, sr[c]);
            red[srow * 10 + stc] = lmax;
        }
        __syncthreads();
        if (tid < 320) {
            int cs = stc * 71, ce = cs + 71; if (ce > 352) ce = 352;
            float* sr = S + srow * SST;
            const float* rr = red + srow * 10;
            float rmax = fmaxf(fmaxf(fmaxf(rr[0], rr[1]), fmaxf(rr[2], rr[3])), rr[4]);
            float lsum = 0.f;
            for (int c = cs; c < ce; c++) {
                float p = __expf(sr[c] - rmax);
                sr[c] = p;
                lsum += p;
            }
            red[srow * 10 + 5 + stc] = lsum;
        }
        __syncthreads();
        if (tid < 64) {
            const float* rr = red + tid * 10 + 5;
            linv[tid] = 1.f / (rr[0] + rr[1] + rr[2] + rr[3] + rr[4]);
        }
        __syncthreads();

        // ---- 4. O = P @ V (thread tile 2 rows x 4 dims, packed) ----
        if (tid < 256) {
            const int r0 = 2 * rg2, r1 = r0 + 1;
            const int dc = 4 * dg;
            u64 o0a = 0ull, o0b = 0ull, o1a = 0ull, o1b = 0ull;
            const float* p0 = S + r0 * SST;
            const float* p1 = S + r1 * SST;
#pragma unroll 7
            for (int m = 0; m < NT; m++) {
                u64 va = *(const u64*)&vs[m * 32 + dc];
                u64 vb = *(const u64*)&vs[m * 32 + dc + 2];
                u64 pa2 = pack2(p0[m], p0[m]);
                u64 pb2 = pack2(p1[m], p1[m]);
                o0a = ffma2(pa2, va, o0a);
                o0b = ffma2(pa2, vb, o0b);
                o1a = ffma2(pb2, va, o1a);
                o1b = ffma2(pb2, vb, o1b);
            }
            int n0 = qbase + r0, n1 = qbase + r1;
            if (n0 < NT) {
                u64 iv = pack2(linv[r0], linv[r0]);
                u64* op = (u64*)&g_attn[((size_t)b * NT + n0) * CDIM + h * HD + dc];
                op[0] = fmul2(o0a, iv); op[1] = fmul2(o0b, iv);
            }
            if (n1 < NT) {
                u64 iv = pack2(linv[r1], linv[r1]);
                u64* op = (u64*)&g_attn[((size_t)b * NT + n1) * CDIM + h * HD + dc];
                op[0] = fmul2(o1a, iv); op[1] = fmul2(o1b, iv);
            }
        }
        __syncthreads();   // S reused by next tile's bias load
    }
}

// ============================ K2: output projection GEMM (4r x 6c tiles) ============================
#define K2_ROWS 64
#define PW_PAD  100
#define SMEM_K2_FLOATS (CDIM*PW_PAD + K2_ROWS*CDIM)

__global__ __launch_bounds__(256)
void proj_kernel(const float* __restrict__ pw,
                 const float* __restrict__ pb,
                 float* __restrict__ out) {
    extern __shared__ float sm2[];
    float* pws = sm2;                          // [c][d], row stride 100
    float* as  = sm2 + CDIM * PW_PAD;          // [r][c], stride 96
    const int tid = threadIdx.x;
    const size_t row0 = (size_t)blockIdx.x * K2_ROWS;

    for (int i = tid; i < CDIM * CDIM; i += 256) {
        pws[(i % CDIM) * PW_PAD + (i / CDIM)] = __ldg(pw + i);
    }
    for (int i = tid; i < K2_ROWS * CDIM; i += 256) {
        as[i] = __ldg(g_attn + row0 * CDIM + i);
    }
    __syncthreads();

    const int rg  = tid >> 4;     // 0..15 -> rows rg*4..+3
    const int cgp = tid & 15;     // cols cgp*6..+5
    const int cb  = cgp * 6;

    u64 acc[4][3];
    u64 b0 = pack2(__ldg(pb + cb + 0), __ldg(pb + cb + 1));
    u64 b1 = pack2(__ldg(pb + cb + 2), __ldg(pb + cb + 3));
    u64 b2 = pack2(__ldg(pb + cb + 4), __ldg(pb + cb + 5));
#pragma unroll
    for (int i = 0; i < 4; i++) { acc[i][0] = b0; acc[i][1] = b1; acc[i][2] = b2; }

#pragma unroll 4
    for (int c = 0; c < CDIM; c++) {
        u64 w0 = *(const u64*)&pws[c * PW_PAD + cb + 0];
        u64 w1 = *(const u64*)&pws[c * PW_PAD + cb + 2];
        u64 w2 = *(const u64*)&pws[c * PW_PAD + cb + 4];
#pragma unroll
        for (int i = 0; i < 4; i++) {
            float xv = as[(rg * 4 + i) * CDIM + c];
            u64 xp = pack2(xv, xv);
            acc[i][0] = ffma2(xp, w0, acc[i][0]);
            acc[i][1] = ffma2(xp, w1, acc[i][1]);
            acc[i][2] = ffma2(xp, w2, acc[i][2]);
        }
    }
#pragma unroll
    for (int i = 0; i < 4; i++) {
        u64* op = (u64*)&out[(row0 + rg * 4 + i) * CDIM + cb];
        op[0] = acc[i][0]; op[1] = acc[i][1]; op[2] = acc[i][2];
    }
}

// ============================ launch ============================
extern "C" void kernel_launch(void* const* d_in, const int* in_sizes, int n_in,
                              void* d_out, int out_size) {
    const float* x      = (const float*)d_in[0];
    const float* mask   = (const float*)d_in[1];
    const float* qkv_w  = (const float*)d_in[2];
    const float* qkv_b  = (const float*)d_in[3];
    const float* proj_w = (const float*)d_in[4];
    const float* proj_b = (const float*)d_in[5];
    const float* rpb    = (const float*)d_in[6];
    const int*   ridx   = (const int*)d_in[7];
    float* out = (float*)d_out;

    cudaFuncSetAttribute(qkv_kernel, cudaFuncAttributeMaxDynamicSharedMemorySize,
                         QKV_SMEM_FLOATS * (int)sizeof(float));
    cudaFuncSetAttribute(attn3_kernel, cudaFuncAttributeMaxDynamicSharedMemorySize,
                         ATTN3_SMEM_FLOATS * (int)sizeof(float));
    cudaFuncSetAttribute(proj_kernel, cudaFuncAttributeMaxDynamicSharedMemorySize,
                         SMEM_K2_FLOATS * (int)sizeof(float));

    bm_kernel<<<dim3((NT * NT + 255) / 256, NW), 256>>>(mask, rpb, ridx);
    qkv_kernel<<<(BTOT * NT) / 128, 256, QKV_SMEM_FLOATS * sizeof(float)>>>(x, qkv_w, qkv_b);
    attn3_kernel<<<dim3(BTOT, NH), 352, ATTN3_SMEM_FLOATS * sizeof(float)>>>();
    proj_kernel<<<(BTOT * NT) / K2_ROWS, 256, SMEM_K2_FLOATS * sizeof(float)>>>(proj_w, proj_b, out);
}